// round 14
// baseline (speedup 1.0000x reference)
#include <cuda_runtime.h>

#define RS2 0.7071067811865476f
#define TAU_V 0.05f

constexpr int SH  = 34;              // float strides (even)
constexpr int SD  = 1090;
constexpr int SH2 = 17;              // float2 strides
constexpr int SD2 = 545;
constexpr int TILE_F = 32 * SD;      // 34880 floats = 139520 B
constexpr int NT = 1024;

// valid level-1 band-block slots (slot = d3*16 + h3*4 + w3, excluding lll octant)
__device__ __constant__ unsigned char VSLOT[56] = {
    2,3,6,7,8,9,10,11,12,13,14,15,18,19,22,23,
    24,25,26,27,28,29,30,31,32,33,34,35,36,37,38,39,
    40,41,42,43,44,45,46,47,48,49,50,51,52,53,54,55,
    56,57,58,59,60,61,62,63
};

extern __shared__ float smem[];

__device__ __forceinline__ float2 f2add(float2 a, float2 b) {
    return make_float2((a.x + b.x) * RS2, (a.y + b.y) * RS2);
}
__device__ __forceinline__ float2 f2sub(float2 a, float2 b) {
    return make_float2((a.x - b.x) * RS2, (a.y - b.y) * RS2);
}

// ---- length-32 half-line pass: thread handles butterflies i = 2t + mu ----
// Pair lanes (mu=0/1) are adjacent in the same warp; __syncwarp orders load->store.
template<int SBASE2, int SLINE2, bool FWD>
__device__ __forceinline__ void pass32_half(float2* T2, int tid) {
    const int slot = tid >> 5, sub = tid & 31;
    const int wp = sub >> 1, mu = sub & 1;
    float2* p = T2 + slot * SBASE2 + wp;
    if (FWD) {
        float2 a[8], b[8];
#pragma unroll
        for (int t = 0; t < 8; t++) {
            a[t] = p[(4*t + 2*mu) * SLINE2];
            b[t] = p[(4*t + 2*mu + 1) * SLINE2];
        }
        __syncwarp();
#pragma unroll
        for (int t = 0; t < 8; t++) {
            const int i = 2*t + mu;
            p[i * SLINE2]        = f2add(a[t], b[t]);
            p[(16 + i) * SLINE2] = f2sub(a[t], b[t]);
        }
    } else {
        float2 lo[8], hi[8];
#pragma unroll
        for (int t = 0; t < 8; t++) {
            const int i = 2*t + mu;
            lo[t] = p[i * SLINE2];
            hi[t] = p[(16 + i) * SLINE2];
        }
        __syncwarp();
#pragma unroll
        for (int t = 0; t < 8; t++) {
            const int i = 2*t + mu;
            p[(2*i) * SLINE2]     = f2add(lo[t], hi[t]);
            p[(2*i + 1) * SLINE2] = f2sub(lo[t], hi[t]);
        }
    }
}

// ---- length-16 half-line (level-2 h/d passes) ----
template<int SLINE2, bool FWD>
__device__ __forceinline__ void line16_half(float2* p, int mu) {
    if (FWD) {
        float2 a[4], b[4];
#pragma unroll
        for (int t = 0; t < 4; t++) {
            a[t] = p[(4*t + 2*mu) * SLINE2];
            b[t] = p[(4*t + 2*mu + 1) * SLINE2];
        }
        __syncwarp();
#pragma unroll
        for (int t = 0; t < 4; t++) {
            const int i = 2*t + mu;
            p[i * SLINE2]       = f2add(a[t], b[t]);
            p[(8 + i) * SLINE2] = f2sub(a[t], b[t]);
        }
    } else {
        float2 lo[4], hi[4];
#pragma unroll
        for (int t = 0; t < 4; t++) {
            const int i = 2*t + mu;
            lo[t] = p[i * SLINE2];
            hi[t] = p[(8 + i) * SLINE2];
        }
        __syncwarp();
#pragma unroll
        for (int t = 0; t < 4; t++) {
            const int i = 2*t + mu;
            p[(2*i) * SLINE2]     = f2add(lo[t], hi[t]);
            p[(2*i + 1) * SLINE2] = f2sub(lo[t], hi[t]);
        }
    }
}

// ---- level-2 w pass, split across a lane pair (512 tasks) ----
template<bool FWD>
__device__ __forceinline__ void l2w_half(float2* T2, int tid) {
    if (tid < 512) {
        const int l = tid >> 1, mu = tid & 1;
        const int d = l >> 4, h = l & 15;
        float2* p = T2 + d * SD2 + h * SH2;
        const int t0 = 2*mu, t1 = 2*mu + 1;
        if (FWD) {
            float2 qa0 = p[4*mu], qb0 = p[4*mu+1], qa1 = p[4*mu+2], qb1 = p[4*mu+3];
            __syncwarp();
            p[t0]   = make_float2((qa0.x + qa0.y)*RS2, (qb0.x + qb0.y)*RS2);
            p[4+t0] = make_float2((qa0.x - qa0.y)*RS2, (qb0.x - qb0.y)*RS2);
            p[t1]   = make_float2((qa1.x + qa1.y)*RS2, (qb1.x + qb1.y)*RS2);
            p[4+t1] = make_float2((qa1.x - qa1.y)*RS2, (qb1.x - qb1.y)*RS2);
        } else {
            float2 lo0 = p[t0], hi0 = p[4+t0], lo1 = p[t1], hi1 = p[4+t1];
            __syncwarp();
            p[2*t0]   = make_float2((lo0.x + hi0.x)*RS2, (lo0.x - hi0.x)*RS2);
            p[2*t0+1] = make_float2((lo0.y + hi0.y)*RS2, (lo0.y - hi0.y)*RS2);
            p[2*t1]   = make_float2((lo1.x + hi1.x)*RS2, (lo1.x - hi1.x)*RS2);
            p[2*t1+1] = make_float2((lo1.y + hi1.y)*RS2, (lo1.y - hi1.y)*RS2);
        }
    }
}

// ---- half-slice 2D Haar pyramid: thread owns global rows [4*par, 4*par+4) of the 8x8 ----
// v[r*8+j], local r in [0,4). Only level-8's i-direction couples the halves (shfl pair).
__device__ __forceinline__ void pyramid_half(float* v, int par, unsigned pm) {
    // fwd level 8, i-direction with pair exchange
#pragma unroll
    for (int j = 0; j < 8; j++) {
        float a0 = v[0*8+j], b0 = v[1*8+j], a1 = v[2*8+j], b1 = v[3*8+j];
        float lo0 = (a0 + b0) * RS2, hi0 = (a0 - b0) * RS2;
        float lo1 = (a1 + b1) * RS2, hi1 = (a1 - b1) * RS2;
        float s0 = par ? lo0 : hi0;
        float s1 = par ? lo1 : hi1;
        float r0 = __shfl_xor_sync(pm, s0, 1);
        float r1 = __shfl_xor_sync(pm, s1, 1);
        if (par == 0) { v[0*8+j] = lo0; v[1*8+j] = lo1; v[2*8+j] = r0;  v[3*8+j] = r1;  }
        else          { v[0*8+j] = r0;  v[1*8+j] = r1;  v[2*8+j] = hi0; v[3*8+j] = hi1; }
    }
    // fwd level 8, j-direction (local rows)
#pragma unroll
    for (int r = 0; r < 4; r++) {
        float t[4], u[4];
#pragma unroll
        for (int c = 0; c < 4; c++) {
            float a = v[r*8 + 2*c], b = v[r*8 + 2*c + 1];
            t[c] = (a + b) * RS2; u[c] = (a - b) * RS2;
        }
#pragma unroll
        for (int c = 0; c < 4; c++) { v[r*8 + c] = t[c]; v[r*8 + 4 + c] = u[c]; }
    }
    // levels 4 and 2 live entirely in par==0 (global rows/cols 0..3)
    if (par == 0) {
#pragma unroll
        for (int j = 0; j < 4; j++) {
            float a0 = v[0+j], b0 = v[8+j], a1 = v[16+j], b1 = v[24+j];
            v[0+j]  = (a0 + b0) * RS2;
            v[8+j]  = (a1 + b1) * RS2;
            v[16+j] = (a0 - b0) * RS2;
            v[24+j] = (a1 - b1) * RS2;
        }
#pragma unroll
        for (int r = 0; r < 4; r++) {
            float a0 = v[r*8+0], b0 = v[r*8+1], a1 = v[r*8+2], b1 = v[r*8+3];
            v[r*8+0] = (a0 + b0) * RS2;
            v[r*8+1] = (a1 + b1) * RS2;
            v[r*8+2] = (a0 - b0) * RS2;
            v[r*8+3] = (a1 - b1) * RS2;
        }
        { float a = v[0], b = v[8]; v[0] = (a+b)*RS2; v[8] = (a-b)*RS2; }
        { float a = v[1], b = v[9]; v[1] = (a+b)*RS2; v[9] = (a-b)*RS2; }
        { float a = v[0], b = v[1]; v[0] = (a+b)*RS2; v[1] = (a-b)*RS2; }
        { float a = v[8], b = v[9]; v[8] = (a+b)*RS2; v[9] = (a-b)*RS2; }
    }
    // soft threshold; DC = par0's v[0]
    float dc = v[0];
#pragma unroll
    for (int e = 0; e < 32; e++)
        v[e] = v[e] - fminf(fmaxf(v[e], -TAU_V), TAU_V);
    if (par == 0) v[0] = dc;
    // inverse levels 2 and 4 (par==0), cols then rows (matches reference)
    if (par == 0) {
        { float lo = v[0], hi = v[1]; v[0] = (lo+hi)*RS2; v[1] = (lo-hi)*RS2; }
        { float lo = v[8], hi = v[9]; v[8] = (lo+hi)*RS2; v[9] = (lo-hi)*RS2; }
        { float lo = v[0], hi = v[8]; v[0] = (lo+hi)*RS2; v[8] = (lo-hi)*RS2; }
        { float lo = v[1], hi = v[9]; v[1] = (lo+hi)*RS2; v[9] = (lo-hi)*RS2; }
#pragma unroll
        for (int r = 0; r < 4; r++) {
            float l0 = v[r*8+0], l1 = v[r*8+1], h0 = v[r*8+2], h1 = v[r*8+3];
            v[r*8+0] = (l0 + h0) * RS2;
            v[r*8+1] = (l0 - h0) * RS2;
            v[r*8+2] = (l1 + h1) * RS2;
            v[r*8+3] = (l1 - h1) * RS2;
        }
#pragma unroll
        for (int j = 0; j < 4; j++) {
            float l0 = v[0+j], l1 = v[8+j], h0 = v[16+j], h1 = v[24+j];
            v[0+j]  = (l0 + h0) * RS2;
            v[8+j]  = (l0 - h0) * RS2;
            v[16+j] = (l1 + h1) * RS2;
            v[24+j] = (l1 - h1) * RS2;
        }
    }
    // inverse level 8, j-direction (local)
#pragma unroll
    for (int r = 0; r < 4; r++) {
        float t[4], u[4];
#pragma unroll
        for (int c = 0; c < 4; c++) {
            float lo = v[r*8 + c], hi = v[r*8 + 4 + c];
            t[c] = (lo + hi) * RS2; u[c] = (lo - hi) * RS2;
        }
#pragma unroll
        for (int c = 0; c < 4; c++) { v[r*8 + 2*c] = t[c]; v[r*8 + 2*c + 1] = u[c]; }
    }
    // inverse level 8, i-direction with pair exchange
#pragma unroll
    for (int j = 0; j < 8; j++) {
        float s0 = par ? v[0*8+j] : v[2*8+j];
        float s1 = par ? v[1*8+j] : v[3*8+j];
        float r0 = __shfl_xor_sync(pm, s0, 1);
        float r1 = __shfl_xor_sync(pm, s1, 1);
        float lo0, hi0, lo1, hi1;
        if (par == 0) { lo0 = v[0*8+j]; hi0 = r0;         lo1 = v[1*8+j]; hi1 = r1;         }
        else          { lo0 = r0;        hi0 = v[2*8+j];  lo1 = r1;        hi1 = v[3*8+j];  }
        v[0*8+j] = (lo0 + hi0) * RS2;
        v[1*8+j] = (lo0 - hi0) * RS2;
        v[2*8+j] = (lo1 + hi1) * RS2;
        v[3*8+j] = (lo1 - hi1) * RS2;
    }
}

// ---- bandlet group (R7 structure): compute all normals, then n0 store / n1 += / n2 merge ----
// One lane pair per slice; each thread handles rows i in [4*par, 4*par+4).
template<bool LEVEL1>
__device__ void bandlet_section(float* T, int tid, int base, int nblk) {
    const int k = tid >> 1, par = tid & 1;
    const int ntask = nblk * 8;
    const unsigned pm = 3u << (threadIdx.x & 30);
    int nrm = 3, s = 0, bd = 0, bh = 0, bw = 0;
    const bool active = k < 3 * ntask;
    if (active) {
        nrm = k / ntask;
        int r = k - nrm * ntask;
        int bg = r >> 3; s = r & 7;
        int slot = LEVEL1 ? (int)VSLOT[base + bg] : (bg + 1);
        if (LEVEL1) { bd = ((slot>>4)&3)*8; bh = ((slot>>2)&3)*8; bw = (slot&3)*8; }
        else        { bd = ((slot>>2)&1)*8; bh = ((slot>>1)&1)*8; bw = (slot&1)*8; }
    }
    float v[32];
    if (active) {
        if (nrm == 0) {
            const float2* p = reinterpret_cast<const float2*>(T + (bd+s)*SD + (bh + 4*par)*SH + bw);
#pragma unroll
            for (int r = 0; r < 4; r++)
#pragma unroll
                for (int jp = 0; jp < 4; jp++) {
                    float2 q = p[r*SH2 + jp];
                    v[r*8 + 2*jp] = q.x; v[r*8 + 2*jp + 1] = q.y;
                }
        } else if (nrm == 1) {
            const float2* p = reinterpret_cast<const float2*>(T + (bd + 4*par)*SD + (bh+s)*SH + bw);
#pragma unroll
            for (int r = 0; r < 4; r++)
#pragma unroll
                for (int jp = 0; jp < 4; jp++) {
                    float2 q = p[r*SD2 + jp];
                    v[r*8 + 2*jp] = q.x; v[r*8 + 2*jp + 1] = q.y;
                }
        } else {
            const float* p = T + (bd + 4*par)*SD + bh*SH + bw + s;
#pragma unroll
            for (int r = 0; r < 4; r++)
#pragma unroll
                for (int j = 0; j < 8; j++) v[r*8+j] = p[r*SD + j*SH];
        }
        pyramid_half(v, par, pm);
    }
    __syncthreads();   // all reads of original band data complete
    if (active && nrm == 0) {
        float2* p = reinterpret_cast<float2*>(T + (bd+s)*SD + (bh + 4*par)*SH + bw);
#pragma unroll
        for (int r = 0; r < 4; r++)
#pragma unroll
            for (int jp = 0; jp < 4; jp++)
                p[r*SH2 + jp] = make_float2(v[r*8 + 2*jp], v[r*8 + 2*jp + 1]);
    }
    __syncthreads();   // n0 visible
    if (active && nrm == 1) {
        float2* p = reinterpret_cast<float2*>(T + (bd + 4*par)*SD + (bh+s)*SH + bw);
#pragma unroll
        for (int r = 0; r < 4; r++)
#pragma unroll
            for (int jp = 0; jp < 4; jp++) {
                float2 q = p[r*SD2 + jp];
                q.x += v[r*8 + 2*jp]; q.y += v[r*8 + 2*jp + 1];
                p[r*SD2 + jp] = q;
            }
    }
    __syncthreads();   // n0+n1 visible
    if (active && nrm == 2) {
        float* p = T + (bd + 4*par)*SD + bh*SH + bw + s;
#pragma unroll
        for (int r = 0; r < 4; r++)
#pragma unroll
            for (int j = 0; j < 8; j++)
                p[r*SD + j*SH] = (p[r*SD + j*SH] + v[r*8+j]) * (1.0f / 3.0f);
    }
    // no trailing barrier: next section's blocks are disjoint regions
}

__global__ __launch_bounds__(NT, 1)
void bandlet3d_kernel(const float* __restrict__ x, float* __restrict__ y) {
    float* T = smem;
    float2* T2 = reinterpret_cast<float2*>(smem);
    const int tid = threadIdx.x;

    const int bc = blockIdx.x;
    const int batch = bc / 125;
    const int rem = bc - batch * 125;
    const int td = rem / 25;
    const int th = (rem / 5) % 5;
    const int tw = rem % 5;
    const long long gbase = (long long)batch * 4096000LL
                          + (long long)td * 32 * 25600 + th * 32 * 160 + tw * 32;

    // ---- fused coalesced load + level-1 w-transform ----
    for (int l = tid; l < 8192; l += NT) {
        int w4 = l & 7, h = (l >> 3) & 31, d = l >> 8;
        float4 q = *reinterpret_cast<const float4*>(x + gbase + d*25600 + h*160 + w4*4);
        float2* p = T2 + d*SD2 + h*SH2;
        p[w4]     = make_float2((q.x + q.y) * RS2, (q.z + q.w) * RS2);
        p[w4 + 8] = make_float2((q.x - q.y) * RS2, (q.z - q.w) * RS2);
    }
    __syncthreads();

    // forward level-1 h and d (1024 half-line tasks each)
    pass32_half<SD2, SH2, true>(T2, tid); __syncthreads();
    pass32_half<SH2, SD2, true>(T2, tid); __syncthreads();

    // ---- level-1 bandlet: 56 blocks in groups of 21/21/14 (1008 half-tasks per group) ----
    bandlet_section<true>(T, tid, 0, 21);
    bandlet_section<true>(T, tid, 21, 21);
    bandlet_section<true>(T, tid, 42, 14);
    // no barrier: fwd level-2 touches only the lll region (disjoint from band blocks)

    // forward level-2 (w, h, d on [0:16)^3)
    l2w_half<true>(T2, tid);                       __syncthreads();
    if (tid < 256) {
        int l = tid >> 1, mu = tid & 1;
        line16_half<SH2, true>(T2 + (l >> 3) * SD2 + (l & 7), mu);
    }
    __syncthreads();
    if (tid < 256) {
        int l = tid >> 1, mu = tid & 1;
        line16_half<SD2, true>(T2 + (l >> 3) * SH2 + (l & 7), mu);
    }
    __syncthreads();

    // ---- level-2 bandlet: 7 blocks (336 half-tasks) ----
    bandlet_section<false>(T, tid, 0, 7);
    __syncthreads();   // inverse level-2 reads the band blocks just written

    // inverse level-2 (d, h, w — axis transforms commute)
    if (tid < 256) {
        int l = tid >> 1, mu = tid & 1;
        line16_half<SD2, false>(T2 + (l >> 3) * SH2 + (l & 7), mu);
    }
    __syncthreads();
    if (tid < 256) {
        int l = tid >> 1, mu = tid & 1;
        line16_half<SH2, false>(T2 + (l >> 3) * SD2 + (l & 7), mu);
    }
    __syncthreads();
    l2w_half<false>(T2, tid);                      __syncthreads();

    // inverse level-1: d, h, then w fused with the store
    pass32_half<SH2, SD2, false>(T2, tid); __syncthreads();
    pass32_half<SD2, SH2, false>(T2, tid); __syncthreads();

    // ---- fused inverse level-1 w-transform + coalesced store ----
    for (int l = tid; l < 8192; l += NT) {
        int w4 = l & 7, h = (l >> 3) & 31, d = l >> 8;
        const float2* p = T2 + d*SD2 + h*SH2;
        float2 lo = p[w4], hi = p[w4 + 8];
        float4 q;
        q.x = (lo.x + hi.x) * RS2; q.y = (lo.x - hi.x) * RS2;
        q.z = (lo.y + hi.y) * RS2; q.w = (lo.y - hi.y) * RS2;
        *reinterpret_cast<float4*>(y + gbase + d*25600 + h*160 + w4*4) = q;
    }
}

extern "C" void kernel_launch(void* const* d_in, const int* in_sizes, int n_in,
                              void* d_out, int out_size) {
    const float* x = (const float*)d_in[0];
    float* y = (float*)d_out;
    (void)in_sizes; (void)n_in; (void)out_size;

    const size_t smem_bytes = (size_t)TILE_F * sizeof(float); // 139520 B
    cudaFuncSetAttribute(bandlet3d_kernel,
                         cudaFuncAttributeMaxDynamicSharedMemorySize, (int)smem_bytes);
    bandlet3d_kernel<<<250, NT, smem_bytes>>>(x, y);
}

// round 15
// speedup vs baseline: 2.0314x; 2.0314x over previous
#include <cuda_runtime.h>

// Unnormalized-forward / half-inverse Haar: fwd butterflies are pure add/sub,
// every inverse directional pass scales by 0.5, thresholds absorb per-region scale.
#define T1A 0.2828427124746190f   // tau * 2^{2.5}  (level-8 coeffs, L1 bands)
#define T1B 0.5656854249492380f   // tau * 2^{3.5}  (level-4 coeffs, L1 bands)
#define T1C 1.1313708498984760f   // tau * 2^{4.5}  (level-2 coeffs, L1 bands)
#define T2A 0.8f                  // tau * 16       (level-8 coeffs, L2 bands)
#define T2B 1.6f                  // tau * 32
#define T2C 3.2f                  // tau * 64

constexpr int SH  = 34;              // float strides (even)
constexpr int SD  = 1090;
constexpr int SH2 = 17;              // float2 strides
constexpr int SD2 = 545;
constexpr int TILE_F = 32 * SD;      // 34880 floats = 139520 B
constexpr int NTHREADS = 512;

// valid level-1 band-block slots (slot = d3*16 + h3*4 + w3, excluding lll octant)
__device__ __constant__ unsigned char VSLOT[56] = {
    2,3,6,7,8,9,10,11,12,13,14,15,18,19,22,23,
    24,25,26,27,28,29,30,31,32,33,34,35,36,37,38,39,
    40,41,42,43,44,45,46,47,48,49,50,51,52,53,54,55,
    56,57,58,59,60,61,62,63
};

extern __shared__ float smem[];

// plain (forward) and half-scaled (inverse) float2 butterfly halves
__device__ __forceinline__ float2 f2addp(float2 a, float2 b) {
    return make_float2(a.x + b.x, a.y + b.y);
}
__device__ __forceinline__ float2 f2subp(float2 a, float2 b) {
    return make_float2(a.x - b.x, a.y - b.y);
}
__device__ __forceinline__ float2 f2addh(float2 a, float2 b) {
    return make_float2((a.x + b.x) * 0.5f, (a.y + b.y) * 0.5f);
}
__device__ __forceinline__ float2 f2subh(float2 a, float2 b) {
    return make_float2((a.x - b.x) * 0.5f, (a.y - b.y) * 0.5f);
}

// ---- generic h/d pass over pairs of adjacent w columns (float2), in place ----
template<int N, int NA, int NW2, int SBASE2, int SLINE2, bool FWD>
__device__ __forceinline__ void pass_hd(float2* T2, int tid) {
    constexpr int NL = NA * NW2;
    if (NL >= NTHREADS || tid < NL) {
        int a = tid / NW2, wp = tid - a * NW2;
        float2* p = T2 + a * SBASE2 + wp;
        float2 v[N];
#pragma unroll
        for (int k = 0; k < N; k++) v[k] = p[k * SLINE2];
#pragma unroll
        for (int i = 0; i < N / 2; i++) {
            if (FWD) {
                p[i * SLINE2]         = f2addp(v[2*i], v[2*i+1]);
                p[(i + N/2) * SLINE2] = f2subp(v[2*i], v[2*i+1]);
            } else {
                p[(2*i) * SLINE2]     = f2addh(v[i], v[i + N/2]);
                p[(2*i + 1) * SLINE2] = f2subh(v[i], v[i + N/2]);
            }
        }
    }
}

// ---- fused d pass: level-1 d everywhere; level-2 d on lll columns ----
template<bool FWD>
__device__ __forceinline__ void pass_d_fused(float2* T2, int tid) {
    const int a = tid >> 4, wp = tid & 15;
    const bool lll = (a < 16) && (wp < 8);
    float2* p = T2 + a * SH2 + wp;
    float2 v[32];
#pragma unroll
    for (int k = 0; k < 32; k++) v[k] = p[k * SD2];
    if (FWD) {
#pragma unroll
        for (int i = 0; i < 16; i++) p[(16 + i) * SD2] = f2subp(v[2*i], v[2*i+1]);
#pragma unroll
        for (int i = 0; i < 16; i++) v[i] = f2addp(v[2*i], v[2*i+1]);
        if (lll) {
#pragma unroll
            for (int i = 0; i < 8; i++) p[(8 + i) * SD2] = f2subp(v[2*i], v[2*i+1]);
#pragma unroll
            for (int i = 0; i < 8; i++) p[i * SD2] = f2addp(v[2*i], v[2*i+1]);
        } else {
#pragma unroll
            for (int i = 0; i < 16; i++) p[i * SD2] = v[i];
        }
    } else {
        if (lll) {
            // composed inverse: L2 inv (x0.5) then L1 inv (x0.5)
#pragma unroll
            for (int i = 0; i < 8; i++) {
                float2 u0 = f2addh(v[i], v[i + 8]);
                float2 u1 = f2subh(v[i], v[i + 8]);
                p[(4*i)     * SD2] = f2addh(u0, v[2*i + 16]);
                p[(4*i + 1) * SD2] = f2subh(u0, v[2*i + 16]);
                p[(4*i + 2) * SD2] = f2addh(u1, v[2*i + 17]);
                p[(4*i + 3) * SD2] = f2subh(u1, v[2*i + 17]);
            }
        } else {
#pragma unroll
            for (int i = 0; i < 16; i++) {
                p[(2*i)     * SD2] = f2addh(v[i], v[i + 16]);
                p[(2*i + 1) * SD2] = f2subh(v[i], v[i + 16]);
            }
        }
    }
}

// ---- level-2 w pass: 16-long lines along w at (d,h) in [0,16)^2, all-float2 ----
template<bool FWD>
__device__ __forceinline__ void pass_w16(float2* T2, int tid) {
    if (tid < 256) {
        int d = tid >> 4, h = tid & 15;
        float2* p = T2 + d * SD2 + h * SH2;
        float2 q[8];
#pragma unroll
        for (int k = 0; k < 8; k++) q[k] = p[k];
        if (FWD) {
#pragma unroll
            for (int t = 0; t < 4; t++) {
                p[t]     = make_float2(q[2*t].x + q[2*t].y, q[2*t+1].x + q[2*t+1].y);
                p[4 + t] = make_float2(q[2*t].x - q[2*t].y, q[2*t+1].x - q[2*t+1].y);
            }
        } else {
#pragma unroll
            for (int t = 0; t < 4; t++) {
                float2 lo = q[t], hi = q[4 + t];
                p[2*t]     = make_float2((lo.x + hi.x) * 0.5f, (lo.x - hi.x) * 0.5f);
                p[2*t + 1] = make_float2((lo.y + hi.y) * 0.5f, (lo.y - hi.y) * 0.5f);
            }
        }
    }
}

// ---- 2D Haar pyramid: unnormalized fwd + region-scaled threshold + half inverse ----
template<int LVL>
__device__ __forceinline__ void pyramid(float* v) {
    // forward: pure add/sub
#pragma unroll
    for (int lev = 0; lev < 3; lev++) {
        const int S = 8 >> lev, H = S >> 1;
#pragma unroll
        for (int j = 0; j < S; j++) {
            float t[4], u[4];
#pragma unroll
            for (int i = 0; i < H; i++) {
                float a = v[(2*i)*8+j], b = v[(2*i+1)*8+j];
                t[i] = a + b; u[i] = a - b;
            }
#pragma unroll
            for (int i = 0; i < H; i++) { v[i*8+j] = t[i]; v[(i+H)*8+j] = u[i]; }
        }
#pragma unroll
        for (int i = 0; i < S; i++) {
            float t[4], u[4];
#pragma unroll
            for (int j = 0; j < H; j++) {
                float a = v[i*8+2*j], b = v[i*8+2*j+1];
                t[j] = a + b; u[j] = a - b;
            }
#pragma unroll
            for (int j = 0; j < H; j++) { v[i*8+j] = t[j]; v[i*8+j+H] = u[j]; }
        }
    }
    // threshold with region-scaled tau (DC e=0 untouched)
#pragma unroll
    for (int e = 1; e < 64; e++) {
        const int i = e >> 3, j = e & 7;
        const float tau = (e == 1 || e == 8 || e == 9) ? (LVL == 1 ? T1C : T2C)
                        : (i < 4 && j < 4)             ? (LVL == 1 ? T1B : T2B)
                                                       : (LVL == 1 ? T1A : T2A);
        v[e] = v[e] - fminf(fmaxf(v[e], -tau), tau);
    }
    // inverse: each directional pass scales by 0.5
#pragma unroll
    for (int lev = 2; lev >= 0; lev--) {
        const int S = 8 >> lev, H = S >> 1;
#pragma unroll
        for (int i = 0; i < S; i++) {
            float t[4], u[4];
#pragma unroll
            for (int j = 0; j < H; j++) {
                float lo = v[i*8+j], hi = v[i*8+j+H];
                t[j] = (lo + hi) * 0.5f; u[j] = (lo - hi) * 0.5f;
            }
#pragma unroll
            for (int j = 0; j < H; j++) { v[i*8+2*j] = t[j]; v[i*8+2*j+1] = u[j]; }
        }
#pragma unroll
        for (int j = 0; j < S; j++) {
            float t[4], u[4];
#pragma unroll
            for (int i = 0; i < H; i++) {
                float lo = v[i*8+j], hi = v[(i+H)*8+j];
                t[i] = (lo + hi) * 0.5f; u[i] = (lo - hi) * 0.5f;
            }
#pragma unroll
            for (int i = 0; i < H; i++) { v[(2*i)*8+j] = t[i]; v[(2*i+1)*8+j] = u[i]; }
        }
    }
}

// R7-style group: compute, then 3 ordered in-T writeback phases.
// No trailing barrier — successive groups touch disjoint block regions.
template<int LVL>
__device__ __forceinline__ void bandlet_group(float* T, int nrm, bool active,
                                              int bd, int bh, int bw, int s) {
    float v[64];
    if (active) {
        if (nrm == 0) {
            const float2* p = reinterpret_cast<const float2*>(T + (bd+s)*SD + bh*SH + bw);
#pragma unroll
            for (int i = 0; i < 8; i++)
#pragma unroll
                for (int jp = 0; jp < 4; jp++) {
                    float2 q = p[i*SH2 + jp];
                    v[i*8 + 2*jp] = q.x; v[i*8 + 2*jp + 1] = q.y;
                }
        } else if (nrm == 1) {
            const float2* p = reinterpret_cast<const float2*>(T + bd*SD + (bh+s)*SH + bw);
#pragma unroll
            for (int i = 0; i < 8; i++)
#pragma unroll
                for (int jp = 0; jp < 4; jp++) {
                    float2 q = p[i*SD2 + jp];
                    v[i*8 + 2*jp] = q.x; v[i*8 + 2*jp + 1] = q.y;
                }
        } else {
            const float* p = T + bd*SD + bh*SH + bw + s;
#pragma unroll
            for (int i = 0; i < 8; i++)
#pragma unroll
                for (int j = 0; j < 8; j++) v[i*8+j] = p[i*SD + j*SH];
        }
        pyramid<LVL>(v);
    }
    __syncthreads();
    if (active && nrm == 0) {
        float2* p = reinterpret_cast<float2*>(T + (bd+s)*SD + bh*SH + bw);
#pragma unroll
        for (int i = 0; i < 8; i++)
#pragma unroll
            for (int jp = 0; jp < 4; jp++)
                p[i*SH2 + jp] = make_float2(v[i*8 + 2*jp], v[i*8 + 2*jp + 1]);
    }
    __syncthreads();
    if (active && nrm == 1) {
        float2* p = reinterpret_cast<float2*>(T + bd*SD + (bh+s)*SH + bw);
#pragma unroll
        for (int i = 0; i < 8; i++)
#pragma unroll
            for (int jp = 0; jp < 4; jp++) {
                float2 q = p[i*SD2 + jp];
                q.x += v[i*8 + 2*jp]; q.y += v[i*8 + 2*jp + 1];
                p[i*SD2 + jp] = q;
            }
    }
    __syncthreads();
    if (active && nrm == 2) {
        float* p = T + bd*SD + bh*SH + bw + s;
#pragma unroll
        for (int i = 0; i < 8; i++)
#pragma unroll
            for (int j = 0; j < 8; j++)
                p[i*SD + j*SH] = (p[i*SD + j*SH] + v[i*8+j]) * (1.0f / 3.0f);
    }
}

__global__ __launch_bounds__(NTHREADS, 1)
void bandlet3d_kernel(const float* __restrict__ x, float* __restrict__ y) {
    float* T = smem;
    float2* T2 = reinterpret_cast<float2*>(smem);
    const int tid = threadIdx.x;

    const int bc = blockIdx.x;
    const int batch = bc / 125;
    const int rem = bc - batch * 125;
    const int td = rem / 25;
    const int th = (rem / 5) % 5;
    const int tw = rem % 5;
    const long long gbase = (long long)batch * 4096000LL
                          + (long long)td * 32 * 25600 + th * 32 * 160 + tw * 32;

    // ---- fused coalesced load + level-1 w-transform (unnormalized) ----
    for (int l = tid; l < 8192; l += NTHREADS) {
        int w4 = l & 7, h = (l >> 3) & 31, d = l >> 8;
        float4 q = *reinterpret_cast<const float4*>(x + gbase + d*25600 + h*160 + w4*4);
        float2* p = T2 + d*SD2 + h*SH2;
        p[w4]     = make_float2(q.x + q.y, q.z + q.w);
        p[w4 + 8] = make_float2(q.x - q.y, q.z - q.w);
    }
    __syncthreads();

    // forward level-1 h, then fused level-1 d + level-2 d (lll columns)
    pass_hd<32, 32, 16, SD2, SH2, true>(T2, tid); __syncthreads();
    pass_d_fused<true>(T2, tid);                  __syncthreads();

    // ---- level-1 bandlet: 56 blocks in groups of 21/21/14 ----
    for (int g = 0; g < 3; g++) {
        const int base = g * 21;
        const int nblk = (g == 2) ? 14 : 21;
        const int ntask = nblk * 8;
        int nrm = 3, s = 0, bd = 0, bh = 0, bw = 0;
        bool active = (tid < 3 * ntask);
        if (active) {
            nrm = tid / ntask;
            int r = tid - nrm * ntask;
            int bg = r >> 3; s = r & 7;
            int slot = VSLOT[base + bg];
            bd = ((slot >> 4) & 3) * 8;
            bh = ((slot >> 2) & 3) * 8;
            bw = (slot & 3) * 8;
        }
        bandlet_group<1>(T, nrm, active, bd, bh, bw, s);
    }
    // no barrier: remaining fwd level-2 passes touch only the lll region (disjoint)

    // forward level-2 h and w (d already applied in the fused pass)
    pass_hd<16, 16, 8, SD2, SH2, true>(T2, tid);  __syncthreads();
    pass_w16<true>(T2, tid);                      __syncthreads();

    // ---- level-2 bandlet: 7 blocks, 168 tasks ----
    {
        int nrm = 3, s = 0, bd = 0, bh = 0, bw = 0;
        bool active = (tid < 168);
        if (active) {
            nrm = tid / 56;
            int r = tid - nrm * 56;
            int bg = r >> 3; s = r & 7;
            int slot = bg + 1;
            bd = ((slot >> 2) & 1) * 8;
            bh = ((slot >> 1) & 1) * 8;
            bw = (slot & 1) * 8;
        }
        bandlet_group<2>(T, nrm, active, bd, bh, bw, s);
    }
    __syncthreads();   // inverse level-2 reads the band blocks just written

    // inverse level-2 w and h (d deferred into the fused inverse pass)
    pass_w16<false>(T2, tid);                      __syncthreads();
    pass_hd<16, 16, 8, SD2, SH2, false>(T2, tid);  __syncthreads();

    // fused inverse: level-2 d (lll) + level-1 d; then h; then w fused with store
    pass_d_fused<false>(T2, tid);                  __syncthreads();
    pass_hd<32, 32, 16, SD2, SH2, false>(T2, tid); __syncthreads();

    // ---- fused inverse level-1 w-transform + coalesced store (x0.5) ----
    for (int l = tid; l < 8192; l += NTHREADS) {
        int w4 = l & 7, h = (l >> 3) & 31, d = l >> 8;
        const float2* p = T2 + d*SD2 + h*SH2;
        float2 lo = p[w4], hi = p[w4 + 8];
        float4 q;
        q.x = (lo.x + hi.x) * 0.5f; q.y = (lo.x - hi.x) * 0.5f;
        q.z = (lo.y + hi.y) * 0.5f; q.w = (lo.y - hi.y) * 0.5f;
        *reinterpret_cast<float4*>(y + gbase + d*25600 + h*160 + w4*4) = q;
    }
}

extern "C" void kernel_launch(void* const* d_in, const int* in_sizes, int n_in,
                              void* d_out, int out_size) {
    const float* x = (const float*)d_in[0];
    float* y = (float*)d_out;
    (void)in_sizes; (void)n_in; (void)out_size;

    const size_t smem_bytes = (size_t)TILE_F * sizeof(float); // 139520 B
    cudaFuncSetAttribute(bandlet3d_kernel,
                         cudaFuncAttributeMaxDynamicSharedMemorySize, (int)smem_bytes);
    bandlet3d_kernel<<<250, NTHREADS, smem_bytes>>>(x, y);
}

// round 16
// speedup vs baseline: 2.1270x; 1.0471x over previous
#include <cuda_runtime.h>

// Fully unnormalized Haar (fwd AND inv butterflies are pure add/sub).
// Scales folded: per-coefficient gamma at threshold; x1/8 in fused-d lll branch
// (covers L2's three dirs); x1/8 at the final store (covers L1's three dirs).
#define T1A 0.2828427124746190f   // tau * 2^{2.5}  (level-8 coeffs, L1 bands)
#define T1B 0.5656854249492380f   // tau * 2^{3.5}  (level-4)
#define T1C 1.1313708498984760f   // tau * 2^{4.5}  (level-2)
#define T2A 0.8f                  // tau * 16       (level-8 coeffs, L2 bands)
#define T2B 1.6f
#define T2C 3.2f

constexpr int SH  = 34;              // float strides (even)
constexpr int SD  = 1090;
constexpr int SH2 = 17;              // float2 strides
constexpr int SD2 = 545;
constexpr int TILE_F = 32 * SD;      // 34880 floats = 139520 B
constexpr int NTHREADS = 512;

__device__ __constant__ unsigned char VSLOT[56] = {
    2,3,6,7,8,9,10,11,12,13,14,15,18,19,22,23,
    24,25,26,27,28,29,30,31,32,33,34,35,36,37,38,39,
    40,41,42,43,44,45,46,47,48,49,50,51,52,53,54,55,
    56,57,58,59,60,61,62,63
};

extern __shared__ float smem[];

__device__ __forceinline__ float2 f2addp(float2 a, float2 b) {
    return make_float2(a.x + b.x, a.y + b.y);
}
__device__ __forceinline__ float2 f2subp(float2 a, float2 b) {
    return make_float2(a.x - b.x, a.y - b.y);
}

// ---- generic h/d pass (float2), pure add/sub both directions ----
template<int N, int NA, int NW2, int SBASE2, int SLINE2, bool FWD>
__device__ __forceinline__ void pass_hd(float2* T2, int tid) {
    constexpr int NL = NA * NW2;
    if (NL >= NTHREADS || tid < NL) {
        int a = tid / NW2, wp = tid - a * NW2;
        float2* p = T2 + a * SBASE2 + wp;
        float2 v[N];
#pragma unroll
        for (int k = 0; k < N; k++) v[k] = p[k * SLINE2];
#pragma unroll
        for (int i = 0; i < N / 2; i++) {
            if (FWD) {
                p[i * SLINE2]         = f2addp(v[2*i], v[2*i+1]);
                p[(i + N/2) * SLINE2] = f2subp(v[2*i], v[2*i+1]);
            } else {
                p[(2*i) * SLINE2]     = f2addp(v[i], v[i + N/2]);
                p[(2*i + 1) * SLINE2] = f2subp(v[i], v[i + N/2]);
            }
        }
    }
}

// ---- fused d pass: level-1 d everywhere; level-2 d on lll columns ----
// Inverse lll branch applies x1/8 (absorbs L2's w+h+d scale); everything else pure.
template<bool FWD>
__device__ __forceinline__ void pass_d_fused(float2* T2, int tid) {
    const int a = tid >> 4, wp = tid & 15;
    const bool lll = (a < 16) && (wp < 8);
    float2* p = T2 + a * SH2 + wp;
    float2 v[32];
#pragma unroll
    for (int k = 0; k < 32; k++) v[k] = p[k * SD2];
    if (FWD) {
#pragma unroll
        for (int i = 0; i < 16; i++) p[(16 + i) * SD2] = f2subp(v[2*i], v[2*i+1]);
#pragma unroll
        for (int i = 0; i < 16; i++) v[i] = f2addp(v[2*i], v[2*i+1]);
        if (lll) {
#pragma unroll
            for (int i = 0; i < 8; i++) p[(8 + i) * SD2] = f2subp(v[2*i], v[2*i+1]);
#pragma unroll
            for (int i = 0; i < 8; i++) p[i * SD2] = f2addp(v[2*i], v[2*i+1]);
        } else {
#pragma unroll
            for (int i = 0; i < 16; i++) p[i * SD2] = v[i];
        }
    } else {
        if (lll) {
#pragma unroll
            for (int i = 0; i < 8; i++) {
                float2 u0 = make_float2((v[i].x + v[i+8].x) * 0.125f,
                                        (v[i].y + v[i+8].y) * 0.125f);
                float2 u1 = make_float2((v[i].x - v[i+8].x) * 0.125f,
                                        (v[i].y - v[i+8].y) * 0.125f);
                p[(4*i)     * SD2] = f2addp(u0, v[2*i + 16]);
                p[(4*i + 1) * SD2] = f2subp(u0, v[2*i + 16]);
                p[(4*i + 2) * SD2] = f2addp(u1, v[2*i + 17]);
                p[(4*i + 3) * SD2] = f2subp(u1, v[2*i + 17]);
            }
        } else {
#pragma unroll
            for (int i = 0; i < 16; i++) {
                p[(2*i)     * SD2] = f2addp(v[i], v[i + 16]);
                p[(2*i + 1) * SD2] = f2subp(v[i], v[i + 16]);
            }
        }
    }
}

// ---- level-2 w pass: pure add/sub both directions ----
template<bool FWD>
__device__ __forceinline__ void pass_w16(float2* T2, int tid) {
    if (tid < 256) {
        int d = tid >> 4, h = tid & 15;
        float2* p = T2 + d * SD2 + h * SH2;
        float2 q[8];
#pragma unroll
        for (int k = 0; k < 8; k++) q[k] = p[k];
        if (FWD) {
#pragma unroll
            for (int t = 0; t < 4; t++) {
                p[t]     = make_float2(q[2*t].x + q[2*t].y, q[2*t+1].x + q[2*t+1].y);
                p[4 + t] = make_float2(q[2*t].x - q[2*t].y, q[2*t+1].x - q[2*t+1].y);
            }
        } else {
#pragma unroll
            for (int t = 0; t < 4; t++) {
                float2 lo = q[t], hi = q[4 + t];
                p[2*t]     = make_float2(lo.x + hi.x, lo.x - hi.x);
                p[2*t + 1] = make_float2(lo.y + hi.y, lo.y - hi.y);
            }
        }
    }
}

// ---- 2D pyramid: pure add/sub fwd, threshold + gamma, pure add/sub inverse ----
template<int LVL>
__device__ __forceinline__ void pyramid(float* v) {
#pragma unroll
    for (int lev = 0; lev < 3; lev++) {
        const int S = 8 >> lev, H = S >> 1;
#pragma unroll
        for (int j = 0; j < S; j++) {
            float t[4], u[4];
#pragma unroll
            for (int i = 0; i < H; i++) {
                float a = v[(2*i)*8+j], b = v[(2*i+1)*8+j];
                t[i] = a + b; u[i] = a - b;
            }
#pragma unroll
            for (int i = 0; i < H; i++) { v[i*8+j] = t[i]; v[(i+H)*8+j] = u[i]; }
        }
#pragma unroll
        for (int i = 0; i < S; i++) {
            float t[4], u[4];
#pragma unroll
            for (int j = 0; j < H; j++) {
                float a = v[i*8+2*j], b = v[i*8+2*j+1];
                t[j] = a + b; u[j] = a - b;
            }
#pragma unroll
            for (int j = 0; j < H; j++) { v[i*8+j] = t[j]; v[i*8+j+H] = u[j]; }
        }
    }
    // threshold with region-scaled tau, then per-region gamma = 2^{-(p+q)/2}
    v[0] *= (1.0f / 64.0f);   // DC: no threshold, gamma only
#pragma unroll
    for (int e = 1; e < 64; e++) {
        const int i = e >> 3, j = e & 7;
        const bool lvl2 = (e == 1 || e == 8 || e == 9);
        const bool lvl4 = (i < 4 && j < 4);
        const float tau = lvl2 ? (LVL == 1 ? T1C : T2C)
                        : lvl4 ? (LVL == 1 ? T1B : T2B)
                               : (LVL == 1 ? T1A : T2A);
        const float gam = lvl2 ? (1.0f / 64.0f) : lvl4 ? (1.0f / 16.0f) : 0.25f;
        v[e] = (v[e] - fminf(fmaxf(v[e], -tau), tau)) * gam;
    }
    // inverse: pure add/sub
#pragma unroll
    for (int lev = 2; lev >= 0; lev--) {
        const int S = 8 >> lev, H = S >> 1;
#pragma unroll
        for (int i = 0; i < S; i++) {
            float t[4], u[4];
#pragma unroll
            for (int j = 0; j < H; j++) {
                float lo = v[i*8+j], hi = v[i*8+j+H];
                t[j] = lo + hi; u[j] = lo - hi;
            }
#pragma unroll
            for (int j = 0; j < H; j++) { v[i*8+2*j] = t[j]; v[i*8+2*j+1] = u[j]; }
        }
#pragma unroll
        for (int j = 0; j < S; j++) {
            float t[4], u[4];
#pragma unroll
            for (int i = 0; i < H; i++) {
                float lo = v[i*8+j], hi = v[(i+H)*8+j];
                t[i] = lo + hi; u[i] = lo - hi;
            }
#pragma unroll
            for (int i = 0; i < H; i++) { v[(2*i)*8+j] = t[i]; v[(2*i+1)*8+j] = u[i]; }
        }
    }
}

// Group with reordered writeback: P2 n2 scalar store, P3 n1 vector add, P4 n0 vector merge.
// No trailing barrier — successive groups touch disjoint block regions.
template<int LVL>
__device__ __forceinline__ void bandlet_group(float* T, int nrm, bool active,
                                              int bd, int bh, int bw, int s) {
    float v[64];
    if (active) {
        if (nrm == 0) {
            const float2* p = reinterpret_cast<const float2*>(T + (bd+s)*SD + bh*SH + bw);
#pragma unroll
            for (int i = 0; i < 8; i++)
#pragma unroll
                for (int jp = 0; jp < 4; jp++) {
                    float2 q = p[i*SH2 + jp];
                    v[i*8 + 2*jp] = q.x; v[i*8 + 2*jp + 1] = q.y;
                }
        } else if (nrm == 1) {
            const float2* p = reinterpret_cast<const float2*>(T + bd*SD + (bh+s)*SH + bw);
#pragma unroll
            for (int i = 0; i < 8; i++)
#pragma unroll
                for (int jp = 0; jp < 4; jp++) {
                    float2 q = p[i*SD2 + jp];
                    v[i*8 + 2*jp] = q.x; v[i*8 + 2*jp + 1] = q.y;
                }
        } else {
            const float* p = T + bd*SD + bh*SH + bw + s;
#pragma unroll
            for (int i = 0; i < 8; i++)
#pragma unroll
                for (int j = 0; j < 8; j++) v[i*8+j] = p[i*SD + j*SH];
        }
        pyramid<LVL>(v);
    }
    __syncthreads();   // all reads of original band data complete
    if (active && nrm == 2) {      // scalar store (overwrites band block)
        float* p = T + bd*SD + bh*SH + bw + s;
#pragma unroll
        for (int i = 0; i < 8; i++)
#pragma unroll
            for (int j = 0; j < 8; j++) p[i*SD + j*SH] = v[i*8+j];
    }
    __syncthreads();   // n2 visible
    if (active && nrm == 1) {      // vector RMW add
        float2* p = reinterpret_cast<float2*>(T + bd*SD + (bh+s)*SH + bw);
#pragma unroll
        for (int i = 0; i < 8; i++)
#pragma unroll
            for (int jp = 0; jp < 4; jp++) {
                float2 q = p[i*SD2 + jp];
                q.x += v[i*8 + 2*jp]; q.y += v[i*8 + 2*jp + 1];
                p[i*SD2 + jp] = q;
            }
    }
    __syncthreads();   // n2+n1 visible
    if (active && nrm == 0) {      // vector merge /3
        float2* p = reinterpret_cast<float2*>(T + (bd+s)*SD + bh*SH + bw);
#pragma unroll
        for (int i = 0; i < 8; i++)
#pragma unroll
            for (int jp = 0; jp < 4; jp++) {
                float2 q = p[i*SH2 + jp];
                q.x = (q.x + v[i*8 + 2*jp])     * (1.0f / 3.0f);
                q.y = (q.y + v[i*8 + 2*jp + 1]) * (1.0f / 3.0f);
                p[i*SH2 + jp] = q;
            }
    }
}

__global__ __launch_bounds__(NTHREADS, 1)
void bandlet3d_kernel(const float* __restrict__ x, float* __restrict__ y) {
    float* T = smem;
    float2* T2 = reinterpret_cast<float2*>(smem);
    const int tid = threadIdx.x;

    const int bc = blockIdx.x;
    const int batch = bc / 125;
    const int rem = bc - batch * 125;
    const int td = rem / 25;
    const int th = (rem / 5) % 5;
    const int tw = rem % 5;
    const long long gbase = (long long)batch * 4096000LL
                          + (long long)td * 32 * 25600 + th * 32 * 160 + tw * 32;

    // ---- fused coalesced load + level-1 w-transform (pure add/sub) ----
    for (int l = tid; l < 8192; l += NTHREADS) {
        int w4 = l & 7, h = (l >> 3) & 31, d = l >> 8;
        float4 q = *reinterpret_cast<const float4*>(x + gbase + d*25600 + h*160 + w4*4);
        float2* p = T2 + d*SD2 + h*SH2;
        p[w4]     = make_float2(q.x + q.y, q.z + q.w);
        p[w4 + 8] = make_float2(q.x - q.y, q.z - q.w);
    }
    __syncthreads();

    // forward level-1 h, then fused level-1 d + level-2 d (lll columns)
    pass_hd<32, 32, 16, SD2, SH2, true>(T2, tid); __syncthreads();
    pass_d_fused<true>(T2, tid);                  __syncthreads();

    // ---- level-1 bandlet: 56 blocks in groups of 21/21/14 ----
    for (int g = 0; g < 3; g++) {
        const int base = g * 21;
        const int nblk = (g == 2) ? 14 : 21;
        const int ntask = nblk * 8;
        int nrm = 3, s = 0, bd = 0, bh = 0, bw = 0;
        bool active = (tid < 3 * ntask);
        if (active) {
            nrm = tid / ntask;
            int r = tid - nrm * ntask;
            int bg = r >> 3; s = r & 7;
            int slot = VSLOT[base + bg];
            bd = ((slot >> 4) & 3) * 8;
            bh = ((slot >> 2) & 3) * 8;
            bw = (slot & 3) * 8;
        }
        bandlet_group<1>(T, nrm, active, bd, bh, bw, s);
    }
    // no barrier: remaining fwd level-2 passes touch only the lll region (disjoint)

    // forward level-2 h and w (d already applied in the fused pass)
    pass_hd<16, 16, 8, SD2, SH2, true>(T2, tid);  __syncthreads();
    pass_w16<true>(T2, tid);                      __syncthreads();

    // ---- level-2 bandlet: 7 blocks, 168 tasks ----
    {
        int nrm = 3, s = 0, bd = 0, bh = 0, bw = 0;
        bool active = (tid < 168);
        if (active) {
            nrm = tid / 56;
            int r = tid - nrm * 56;
            int bg = r >> 3; s = r & 7;
            int slot = bg + 1;
            bd = ((slot >> 2) & 1) * 8;
            bh = ((slot >> 1) & 1) * 8;
            bw = (slot & 1) * 8;
        }
        bandlet_group<2>(T, nrm, active, bd, bh, bw, s);
    }
    __syncthreads();   // inverse level-2 reads the band blocks just written

    // inverse level-2 w and h (pure; scale folded into fused-d lll branch)
    pass_w16<false>(T2, tid);                      __syncthreads();
    pass_hd<16, 16, 8, SD2, SH2, false>(T2, tid);  __syncthreads();

    // fused inverse: level-2 d (x1/8) + level-1 d (pure); then h (pure); then w + store (x1/8)
    pass_d_fused<false>(T2, tid);                  __syncthreads();
    pass_hd<32, 32, 16, SD2, SH2, false>(T2, tid); __syncthreads();

    // ---- fused inverse level-1 w-transform + coalesced store (x1/8 for L1's 3 dirs) ----
    for (int l = tid; l < 8192; l += NTHREADS) {
        int w4 = l & 7, h = (l >> 3) & 31, d = l >> 8;
        const float2* p = T2 + d*SD2 + h*SH2;
        float2 lo = p[w4], hi = p[w4 + 8];
        float4 q;
        q.x = (lo.x + hi.x) * 0.125f; q.y = (lo.x - hi.x) * 0.125f;
        q.z = (lo.y + hi.y) * 0.125f; q.w = (lo.y - hi.y) * 0.125f;
        *reinterpret_cast<float4*>(y + gbase + d*25600 + h*160 + w4*4) = q;
    }
}

extern "C" void kernel_launch(void* const* d_in, const int* in_sizes, int n_in,
                              void* d_out, int out_size) {
    const float* x = (const float*)d_in[0];
    float* y = (float*)d_out;
    (void)in_sizes; (void)n_in; (void)out_size;

    const size_t smem_bytes = (size_t)TILE_F * sizeof(float); // 139520 B
    cudaFuncSetAttribute(bandlet3d_kernel,
                         cudaFuncAttributeMaxDynamicSharedMemorySize, (int)smem_bytes);
    bandlet3d_kernel<<<250, NTHREADS, smem_bytes>>>(x, y);
}

// round 17
// speedup vs baseline: 2.2186x; 1.0430x over previous
#include <cuda_runtime.h>

// Fully unnormalized Haar (fwd AND inv butterflies pure add/sub).
// Scales folded: per-coefficient gamma at threshold; x1/8 in fused-d lll branch;
// x1/8 at the final store.
#define T1A 0.2828427124746190f   // tau * 2^{2.5}  (level-8 coeffs, L1 bands)
#define T1B 0.5656854249492380f   // tau * 2^{3.5}
#define T1C 1.1313708498984760f   // tau * 2^{4.5}
#define T2A 0.8f                  // tau * 16       (level-8 coeffs, L2 bands)
#define T2B 1.6f
#define T2C 3.2f

constexpr int SH  = 34;              // float strides (even)
constexpr int SD  = 1090;
constexpr int SH2 = 17;              // float2 strides
constexpr int SD2 = 545;
constexpr int TILE_F = 32 * SD;      // 34880 floats
constexpr int SBF  = 520;            // scratch block stride (<=> 8 mod 32; layout d*65+h*8+w)
constexpr int SHALF = 21 * SBF;      // 10920 floats per scratch half
constexpr int NTHREADS = 512;

__device__ __constant__ unsigned char VSLOT[56] = {
    2,3,6,7,8,9,10,11,12,13,14,15,18,19,22,23,
    24,25,26,27,28,29,30,31,32,33,34,35,36,37,38,39,
    40,41,42,43,44,45,46,47,48,49,50,51,52,53,54,55,
    56,57,58,59,60,61,62,63
};

extern __shared__ float smem[];

__device__ __forceinline__ float2 f2addp(float2 a, float2 b) {
    return make_float2(a.x + b.x, a.y + b.y);
}
__device__ __forceinline__ float2 f2subp(float2 a, float2 b) {
    return make_float2(a.x - b.x, a.y - b.y);
}

// ---- generic h/d pass (float2), pure add/sub both directions ----
template<int N, int NA, int NW2, int SBASE2, int SLINE2, bool FWD>
__device__ __forceinline__ void pass_hd(float2* T2, int tid) {
    constexpr int NL = NA * NW2;
    if (NL >= NTHREADS || tid < NL) {
        int a = tid / NW2, wp = tid - a * NW2;
        float2* p = T2 + a * SBASE2 + wp;
        float2 v[N];
#pragma unroll
        for (int k = 0; k < N; k++) v[k] = p[k * SLINE2];
#pragma unroll
        for (int i = 0; i < N / 2; i++) {
            if (FWD) {
                p[i * SLINE2]         = f2addp(v[2*i], v[2*i+1]);
                p[(i + N/2) * SLINE2] = f2subp(v[2*i], v[2*i+1]);
            } else {
                p[(2*i) * SLINE2]     = f2addp(v[i], v[i + N/2]);
                p[(2*i + 1) * SLINE2] = f2subp(v[i], v[i + N/2]);
            }
        }
    }
}

// ---- fused d pass: level-1 d everywhere; level-2 d on lll columns ----
template<bool FWD>
__device__ __forceinline__ void pass_d_fused(float2* T2, int tid) {
    const int a = tid >> 4, wp = tid & 15;
    const bool lll = (a < 16) && (wp < 8);
    float2* p = T2 + a * SH2 + wp;
    float2 v[32];
#pragma unroll
    for (int k = 0; k < 32; k++) v[k] = p[k * SD2];
    if (FWD) {
#pragma unroll
        for (int i = 0; i < 16; i++) p[(16 + i) * SD2] = f2subp(v[2*i], v[2*i+1]);
#pragma unroll
        for (int i = 0; i < 16; i++) v[i] = f2addp(v[2*i], v[2*i+1]);
        if (lll) {
#pragma unroll
            for (int i = 0; i < 8; i++) p[(8 + i) * SD2] = f2subp(v[2*i], v[2*i+1]);
#pragma unroll
            for (int i = 0; i < 8; i++) p[i * SD2] = f2addp(v[2*i], v[2*i+1]);
        } else {
#pragma unroll
            for (int i = 0; i < 16; i++) p[i * SD2] = v[i];
        }
    } else {
        if (lll) {
#pragma unroll
            for (int i = 0; i < 8; i++) {
                float2 u0 = make_float2((v[i].x + v[i+8].x) * 0.125f,
                                        (v[i].y + v[i+8].y) * 0.125f);
                float2 u1 = make_float2((v[i].x - v[i+8].x) * 0.125f,
                                        (v[i].y - v[i+8].y) * 0.125f);
                p[(4*i)     * SD2] = f2addp(u0, v[2*i + 16]);
                p[(4*i + 1) * SD2] = f2subp(u0, v[2*i + 16]);
                p[(4*i + 2) * SD2] = f2addp(u1, v[2*i + 17]);
                p[(4*i + 3) * SD2] = f2subp(u1, v[2*i + 17]);
            }
        } else {
#pragma unroll
            for (int i = 0; i < 16; i++) {
                p[(2*i)     * SD2] = f2addp(v[i], v[i + 16]);
                p[(2*i + 1) * SD2] = f2subp(v[i], v[i + 16]);
            }
        }
    }
}

// ---- level-2 w pass: pure add/sub both directions ----
template<bool FWD>
__device__ __forceinline__ void pass_w16(float2* T2, int tid) {
    if (tid < 256) {
        int d = tid >> 4, h = tid & 15;
        float2* p = T2 + d * SD2 + h * SH2;
        float2 q[8];
#pragma unroll
        for (int k = 0; k < 8; k++) q[k] = p[k];
        if (FWD) {
#pragma unroll
            for (int t = 0; t < 4; t++) {
                p[t]     = make_float2(q[2*t].x + q[2*t].y, q[2*t+1].x + q[2*t+1].y);
                p[4 + t] = make_float2(q[2*t].x - q[2*t].y, q[2*t+1].x - q[2*t+1].y);
            }
        } else {
#pragma unroll
            for (int t = 0; t < 4; t++) {
                float2 lo = q[t], hi = q[4 + t];
                p[2*t]     = make_float2(lo.x + hi.x, lo.x - hi.x);
                p[2*t + 1] = make_float2(lo.y + hi.y, lo.y - hi.y);
            }
        }
    }
}

// ---- 2D pyramid: pure add/sub fwd, threshold + gamma, pure add/sub inverse ----
template<int LVL>
__device__ __forceinline__ void pyramid(float* v) {
#pragma unroll
    for (int lev = 0; lev < 3; lev++) {
        const int S = 8 >> lev, H = S >> 1;
#pragma unroll
        for (int j = 0; j < S; j++) {
            float t[4], u[4];
#pragma unroll
            for (int i = 0; i < H; i++) {
                float a = v[(2*i)*8+j], b = v[(2*i+1)*8+j];
                t[i] = a + b; u[i] = a - b;
            }
#pragma unroll
            for (int i = 0; i < H; i++) { v[i*8+j] = t[i]; v[(i+H)*8+j] = u[i]; }
        }
#pragma unroll
        for (int i = 0; i < S; i++) {
            float t[4], u[4];
#pragma unroll
            for (int j = 0; j < H; j++) {
                float a = v[i*8+2*j], b = v[i*8+2*j+1];
                t[j] = a + b; u[j] = a - b;
            }
#pragma unroll
            for (int j = 0; j < H; j++) { v[i*8+j] = t[j]; v[i*8+j+H] = u[j]; }
        }
    }
    v[0] *= (1.0f / 64.0f);
#pragma unroll
    for (int e = 1; e < 64; e++) {
        const int i = e >> 3, j = e & 7;
        const bool lvl2 = (e == 1 || e == 8 || e == 9);
        const bool lvl4 = (i < 4 && j < 4);
        const float tau = lvl2 ? (LVL == 1 ? T1C : T2C)
                        : lvl4 ? (LVL == 1 ? T1B : T2B)
                               : (LVL == 1 ? T1A : T2A);
        const float gam = lvl2 ? (1.0f / 64.0f) : lvl4 ? (1.0f / 16.0f) : 0.25f;
        v[e] = (v[e] - fminf(fmaxf(v[e], -tau), tau)) * gam;
    }
#pragma unroll
    for (int lev = 2; lev >= 0; lev--) {
        const int S = 8 >> lev, H = S >> 1;
#pragma unroll
        for (int i = 0; i < S; i++) {
            float t[4], u[4];
#pragma unroll
            for (int j = 0; j < H; j++) {
                float lo = v[i*8+j], hi = v[i*8+j+H];
                t[j] = lo + hi; u[j] = lo - hi;
            }
#pragma unroll
            for (int j = 0; j < H; j++) { v[i*8+2*j] = t[j]; v[i*8+2*j+1] = u[j]; }
        }
#pragma unroll
        for (int j = 0; j < S; j++) {
            float t[4], u[4];
#pragma unroll
            for (int i = 0; i < H; i++) {
                float lo = v[i*8+j], hi = v[(i+H)*8+j];
                t[i] = lo + hi; u[i] = lo - hi;
            }
#pragma unroll
            for (int i = 0; i < H; i++) { v[(2*i)*8+j] = t[i]; v[(2*i+1)*8+j] = u[i]; }
        }
    }
}

// ---- 2-barrier group: [compute; n2->scratch] B [n1 -> T plain store] B [n0: T=(v+T+S)/3] ----
// Scratch layout: sbase + d*65 + h*8 + w (conflict-free for n2 write & n0 read).
// No trailing barrier: groups alternate scratch halves; region-disjointness covers T.
template<int LVL>
__device__ __forceinline__ void bandlet_group(float* T, float* S, int tid, int base, int nblk) {
    const int ntask = nblk * 8;
    int nrm = 3, s = 0, bd = 0, bh = 0, bw = 0, sbase = 0;
    const bool active = (tid < 3 * ntask);
    if (active) {
        nrm = tid / ntask;
        int r = tid - nrm * ntask;
        int bg = r >> 3; s = r & 7;
        sbase = bg * SBF;
        int slot = (LVL == 1) ? (int)VSLOT[base + bg] : (bg + 1);
        if (LVL == 1) { bd = ((slot>>4)&3)*8; bh = ((slot>>2)&3)*8; bw = (slot&3)*8; }
        else          { bd = ((slot>>2)&1)*8; bh = ((slot>>1)&1)*8; bw = (slot&1)*8; }
    }
    float v[64];
    if (active) {
        if (nrm == 0) {
            const float2* p = reinterpret_cast<const float2*>(T + (bd+s)*SD + bh*SH + bw);
#pragma unroll
            for (int i = 0; i < 8; i++)
#pragma unroll
                for (int jp = 0; jp < 4; jp++) {
                    float2 q = p[i*SH2 + jp];
                    v[i*8 + 2*jp] = q.x; v[i*8 + 2*jp + 1] = q.y;
                }
        } else if (nrm == 1) {
            const float2* p = reinterpret_cast<const float2*>(T + bd*SD + (bh+s)*SH + bw);
#pragma unroll
            for (int i = 0; i < 8; i++)
#pragma unroll
                for (int jp = 0; jp < 4; jp++) {
                    float2 q = p[i*SD2 + jp];
                    v[i*8 + 2*jp] = q.x; v[i*8 + 2*jp + 1] = q.y;
                }
        } else {
            const float* p = T + bd*SD + bh*SH + bw + s;
#pragma unroll
            for (int i = 0; i < 8; i++)
#pragma unroll
                for (int j = 0; j < 8; j++) v[i*8+j] = p[i*SD + j*SH];
        }
        pyramid<LVL>(v);
        if (nrm == 2) {
            // r2 -> scratch (element (d=i, h=j, w=s)), disjoint from T: no barrier needed
            float* q = S + sbase + s;
#pragma unroll
            for (int i = 0; i < 8; i++)
#pragma unroll
                for (int j = 0; j < 8; j++)
                    q[i*65 + j*8] = v[i*8+j];
        }
    }
    __syncthreads();   // all reads of original band data done; r2 in scratch
    if (active && nrm == 1) {      // overwrite block with r1 (plain vector store)
        float2* p = reinterpret_cast<float2*>(T + bd*SD + (bh+s)*SH + bw);
#pragma unroll
        for (int i = 0; i < 8; i++)
#pragma unroll
            for (int jp = 0; jp < 4; jp++)
                p[i*SD2 + jp] = make_float2(v[i*8 + 2*jp], v[i*8 + 2*jp + 1]);
    }
    __syncthreads();   // r1 visible
    if (active && nrm == 0) {      // T = (r0 + r1 + r2) / 3
        float2* p = reinterpret_cast<float2*>(T + (bd+s)*SD + bh*SH + bw);
        const float* q = S + sbase + s * 65;
#pragma unroll
        for (int i = 0; i < 8; i++)
#pragma unroll
            for (int jp = 0; jp < 4; jp++) {
                float2 t = p[i*SH2 + jp];
                t.x = (t.x + q[i*8 + 2*jp]     + v[i*8 + 2*jp])     * (1.0f / 3.0f);
                t.y = (t.y + q[i*8 + 2*jp + 1] + v[i*8 + 2*jp + 1]) * (1.0f / 3.0f);
                p[i*SH2 + jp] = t;
            }
    }
}

__global__ __launch_bounds__(NTHREADS, 1)
void bandlet3d_kernel(const float* __restrict__ x, float* __restrict__ y) {
    float* T = smem;
    float2* T2 = reinterpret_cast<float2*>(smem);
    float* SA = smem + TILE_F;          // scratch half A
    float* SB = SA + SHALF;             // scratch half B
    const int tid = threadIdx.x;

    const int bc = blockIdx.x;
    const int batch = bc / 125;
    const int rem = bc - batch * 125;
    const int td = rem / 25;
    const int th = (rem / 5) % 5;
    const int tw = rem % 5;
    const long long gbase = (long long)batch * 4096000LL
                          + (long long)td * 32 * 25600 + th * 32 * 160 + tw * 32;

    // ---- fused coalesced load + level-1 w-transform (strength-reduced) ----
    {
        const int w4 = tid & 7, h = (tid >> 3) & 31, d0 = tid >> 8;
        const float* gp = x + gbase + d0*25600 + h*160 + w4*4;
        float2* p = T2 + d0*SD2 + h*SH2 + w4;
#pragma unroll
        for (int it = 0; it < 16; it++) {
            float4 q = *reinterpret_cast<const float4*>(gp + it*2*25600);
            p[it*2*SD2]     = make_float2(q.x + q.y, q.z + q.w);
            p[it*2*SD2 + 8] = make_float2(q.x - q.y, q.z - q.w);
        }
    }
    __syncthreads();

    // forward level-1 h, then fused level-1 d + level-2 d (lll columns)
    pass_hd<32, 32, 16, SD2, SH2, true>(T2, tid); __syncthreads();
    pass_d_fused<true>(T2, tid);                  __syncthreads();

    // ---- level-1 bandlet: 56 blocks in groups of 21/21/14 (alternating scratch halves) ----
    bandlet_group<1>(T, SA, tid, 0, 21);
    bandlet_group<1>(T, SB, tid, 21, 21);
    bandlet_group<1>(T, SA, tid, 42, 14);
    // no barrier: fwd level-2 passes touch only the lll region (disjoint from band blocks)

    // forward level-2 h and w (d already applied in the fused pass)
    pass_hd<16, 16, 8, SD2, SH2, true>(T2, tid);  __syncthreads();
    pass_w16<true>(T2, tid);                      __syncthreads();

    // ---- level-2 bandlet: 7 blocks (scratch half B — half A last read by group 3) ----
    bandlet_group<2>(T, SB, tid, 0, 7);
    __syncthreads();   // inverse level-2 reads the band blocks just merged

    // inverse level-2 w and h (pure; scale folded into fused-d lll branch)
    pass_w16<false>(T2, tid);                      __syncthreads();
    pass_hd<16, 16, 8, SD2, SH2, false>(T2, tid);  __syncthreads();

    // fused inverse: level-2 d (x1/8) + level-1 d (pure); then h (pure); then w + store (x1/8)
    pass_d_fused<false>(T2, tid);                  __syncthreads();
    pass_hd<32, 32, 16, SD2, SH2, false>(T2, tid); __syncthreads();

    // ---- fused inverse level-1 w-transform + coalesced store (strength-reduced) ----
    {
        const int w4 = tid & 7, h = (tid >> 3) & 31, d0 = tid >> 8;
        float* gp = y + gbase + d0*25600 + h*160 + w4*4;
        const float2* p = T2 + d0*SD2 + h*SH2 + w4;
#pragma unroll
        for (int it = 0; it < 16; it++) {
            float2 lo = p[it*2*SD2], hi = p[it*2*SD2 + 8];
            float4 q;
            q.x = (lo.x + hi.x) * 0.125f; q.y = (lo.x - hi.x) * 0.125f;
            q.z = (lo.y + hi.y) * 0.125f; q.w = (lo.y - hi.y) * 0.125f;
            *reinterpret_cast<float4*>(gp + it*2*25600) = q;
        }
    }
}

extern "C" void kernel_launch(void* const* d_in, const int* in_sizes, int n_in,
                              void* d_out, int out_size) {
    const float* x = (const float*)d_in[0];
    float* y = (float*)d_out;
    (void)in_sizes; (void)n_in; (void)out_size;

    const size_t smem_bytes = (size_t)(TILE_F + 2 * SHALF) * sizeof(float); // 226880 B
    cudaFuncSetAttribute(bandlet3d_kernel,
                         cudaFuncAttributeMaxDynamicSharedMemorySize, (int)smem_bytes);
    bandlet3d_kernel<<<250, NTHREADS, smem_bytes>>>(x, y);
}